// round 7
// baseline (speedup 1.0000x reference)
#include <cuda_runtime.h>
#include <cuda_fp16.h>
#include <mma.h>
#include <math.h>

using namespace nvcuda;

#define NN   50000
#define NNP  50048           // padded to multiple of 64
#define EE   800000
#define INF_ 128
#define H    8
#define HIDD 32
#define OUTD 16
#define C1   (H*HIDD)   // 256
#define C2   (H*OUT D)  // placeholder avoided
#undef C2
#define C2   (H*OUTD)   // 128

// ---------------- scratch (device globals, zero-initialized) ----------------
__device__ __half g_x16  [(size_t)NNP * INF_];
__device__ __half g_W1_16[INF_ * C1];
__device__ __half g_W2_16[C1 * C2];
__device__ __half g_feat1[(size_t)NNP * C1];
__device__ __half g_agg1 [(size_t)NNP * C1];   // fp16: GEMM2 input
__device__ __half g_feat2[(size_t)NNP * C2];
__device__ float  g_el   [NN * H];
__device__ float  g_er   [NN * H];
__device__ int    g_csr  [EE];
__device__ int    g_rowstart[NN + 1];
__device__ int    g_cnt  [NN];

// ---------------- CSR build --------------------------------------------------
__global__ void k_zero_cnt() {
    int i = blockIdx.x * blockDim.x + threadIdx.x;
    if (i < NN) g_cnt[i] = 0;
}
__global__ void k_hist(const int* __restrict__ dst) {
    int e = blockIdx.x * blockDim.x + threadIdx.x;
    if (e < EE) atomicAdd(&g_cnt[dst[e]], 1);
}
__global__ void k_scan() {
    const int T = 1024;
    const int CH = (NN + T - 1) / T;
    int t = threadIdx.x;
    int base = t * CH;
    int s = 0;
#pragma unroll 4
    for (int i = 0; i < CH; i++) {
        int idx = base + i;
        if (idx < NN) s += g_cnt[idx];
    }
    __shared__ int sh[T];
    sh[t] = s;
    __syncthreads();
    for (int off = 1; off < T; off <<= 1) {
        int v = (t >= off) ? sh[t - off] : 0;
        __syncthreads();
        sh[t] += v;
        __syncthreads();
    }
    int run = sh[t] - s;
    for (int i = 0; i < CH; i++) {
        int idx = base + i;
        if (idx < NN) {
            int c = g_cnt[idx];
            g_rowstart[idx] = run;
            g_cnt[idx] = run;
            run += c;
        }
    }
    if (t == 0) g_rowstart[NN] = EE;
}
__global__ void k_scatter(const int* __restrict__ src, const int* __restrict__ dst) {
    int e = blockIdx.x * blockDim.x + threadIdx.x;
    if (e >= EE) return;
    int p = atomicAdd(&g_cnt[dst[e]], 1);
    g_csr[p] = src[e];
}

// ---------------- fp16 conversions (x, W1, W2 in one kernel) -----------------
__global__ void k_convert(const float* __restrict__ x, const float* __restrict__ W1,
                          const float* __restrict__ W2) {
    int i = blockIdx.x * blockDim.x + threadIdx.x;
    if (i < NN * INF_) g_x16[i] = __float2half_rn(x[i]);
    if (i < INF_ * C1) g_W1_16[i] = __float2half_rn(W1[i]);
    if (i < C1 * C2)   g_W2_16[i] = __float2half_rn(W2[i]);
}

// ---------------- tensor-core GEMM + attention epilogue ----------------------
template<int K, int NC, int D>
__global__ void gemm_att_wmma(const __half* __restrict__ A, const __half* __restrict__ Wm,
                              const float* __restrict__ al, const float* __restrict__ ar,
                              __half* __restrict__ feat, float* __restrict__ el,
                              float* __restrict__ er, int n)
{
    extern __shared__ float sm[];    // 64 * NC floats
    constexpr int NSPAN = NC / 2;
    constexpr int NFRAG = NSPAN / 16;

    int wid = threadIdx.x >> 5;
    int warp_m = wid & 3;
    int warp_n = wid >> 2;
    int m0 = blockIdx.x * 64 + warp_m * 16;

    wmma::fragment<wmma::accumulator, 16, 16, 16, float> c[NFRAG];
#pragma unroll
    for (int f = 0; f < NFRAG; f++) wmma::fill_fragment(c[f], 0.f);

    for (int k = 0; k < K; k += 16) {
        wmma::fragment<wmma::matrix_a, 16, 16, 16, __half, wmma::row_major> a;
        wmma::load_matrix_sync(a, A + (size_t)m0 * K + k, K);
#pragma unroll
        for (int f = 0; f < NFRAG; f++) {
            wmma::fragment<wmma::matrix_b, 16, 16, 16, __half, wmma::row_major> b;
            wmma::load_matrix_sync(b, Wm + (size_t)k * NC + warp_n * NSPAN + f * 16, NC);
            wmma::mma_sync(c[f], a, b, c[f]);
        }
    }

#pragma unroll
    for (int f = 0; f < NFRAG; f++)
        wmma::store_matrix_sync(sm + warp_m * 16 * NC + warp_n * NSPAN + f * 16,
                                c[f], NC, wmma::mem_row_major);
    __syncthreads();

    constexpr int RPT = NC / 4;
    int j = threadIdx.x % NC;
    int r0 = (threadIdx.x / NC) * RPT;
    float alj = al[j], arj = ar[j];
    int head = j / D;
    for (int r = r0; r < r0 + RPT; r++) {
        int row = blockIdx.x * 64 + r;
        float v = sm[r * NC + j];
        bool valid = row < n;
        if (valid) feat[(size_t)row * NC + j] = __float2half_rn(v);
        float ev = v * alj;
        float rv = v * arj;
#pragma unroll
        for (int off = D / 2; off > 0; off >>= 1) {
            ev += __shfl_xor_sync(0xffffffffu, ev, off);
            rv += __shfl_xor_sync(0xffffffffu, rv, off);
        }
        if ((j % D) == 0 && valid) {
            el[row * H + head] = ev;
            er[row * H + head] = rv;
        }
    }
}

// ---------------- fused per-node softmax + aggregate (single pass) ----------
// WPN warps cooperate on one dst node, each owning DT/WPN columns (disjoint).
// Each warp recomputes the (identical) exp-sum — no cross-warp reduction.
// V = columns per lane = DT/(32*WPN) = 4; loads are uint2 (4 halves).
template<int DT, int WPN, bool ELU, bool FINAL>
__global__ void node_aggregate(const __half* __restrict__ feat,
                               const float* __restrict__ el,
                               const float* __restrict__ er,
                               const float* __restrict__ bias,
                               void* __restrict__ outp)
{
    int gwid = blockIdx.x * (blockDim.x >> 5) + (threadIdx.x >> 5);
    int d = gwid / WPN;
    int w = gwid % WPN;
    if (d >= NN) return;
    int lane = threadIdx.x & 31;
    constexpr int COLS = DT / WPN;
    constexpr int V = COLS / 32;      // 4
    constexpr int NH2 = V / 2;        // 2
    int colbase = w * COLS;
    int head = (colbase + lane * V) / (DT / H);

    int beg = g_rowstart[d], end = g_rowstart[d + 1];

    float sum = 0.f;
    float acc[V];
#pragma unroll
    for (int k = 0; k < V; k++) acc[k] = 0.f;

    float erv = (beg < end) ? er[d * H + head] : 0.f;

    const __half* fbase = feat + colbase;

    int i = beg;
    for (; i + 3 < end; i += 4) {
        int s0 = g_csr[i+0], s1 = g_csr[i+1], s2 = g_csr[i+2], s3 = g_csr[i+3];
        float l0 = el[s0 * H + head];
        float l1 = el[s1 * H + head];
        float l2 = el[s2 * H + head];
        float l3 = el[s3 * H + head];
        __half2 v0[NH2], v1[NH2], v2[NH2], v3[NH2];
        *(uint2*)v0 = *(const uint2*)((const __half2*)(fbase + (size_t)s0 * DT) + lane * NH2);
        *(uint2*)v1 = *(const uint2*)((const __half2*)(fbase + (size_t)s1 * DT) + lane * NH2);
        *(uint2*)v2 = *(const uint2*)((const __half2*)(fbase + (size_t)s2 * DT) + lane * NH2);
        *(uint2*)v3 = *(const uint2*)((const __half2*)(fbase + (size_t)s3 * DT) + lane * NH2);
        l0 += erv; l1 += erv; l2 += erv; l3 += erv;
        l0 = l0 > 0.f ? l0 : 0.2f * l0;
        l1 = l1 > 0.f ? l1 : 0.2f * l1;
        l2 = l2 > 0.f ? l2 : 0.2f * l2;
        l3 = l3 > 0.f ? l3 : 0.2f * l3;
        float w0 = __expf(l0), w1 = __expf(l1), w2 = __expf(l2), w3 = __expf(l3);
        sum += (w0 + w1) + (w2 + w3);
#pragma unroll
        for (int k = 0; k < NH2; k++) {
            float2 a0 = __half22float2(v0[k]);
            float2 a1 = __half22float2(v1[k]);
            float2 a2 = __half22float2(v2[k]);
            float2 a3 = __half22float2(v3[k]);
            acc[k*2+0] += w0*a0.x + w1*a1.x + w2*a2.x + w3*a3.x;
            acc[k*2+1] += w0*a0.y + w1*a1.y + w2*a2.y + w3*a3.y;
        }
    }
    for (; i < end; i++) {
        int s = g_csr[i];
        float l = el[s * H + head] + erv;
        l = l > 0.f ? l : 0.2f * l;
        float wgt = __expf(l);
        sum += wgt;
        __half2 v[NH2];
        *(uint2*)v = *(const uint2*)((const __half2*)(fbase + (size_t)s * DT) + lane * NH2);
#pragma unroll
        for (int k = 0; k < NH2; k++) {
            float2 a = __half22float2(v[k]);
            acc[k*2+0] += wgt * a.x;
            acc[k*2+1] += wgt * a.y;
        }
    }

    float inv = (beg < end) ? 1.f / sum : 0.f;

    float vals[V];
#pragma unroll
    for (int k = 0; k < V; k++) {
        float v = acc[k] * inv + bias[colbase + lane * V + k];
        vals[k] = ELU ? (v > 0.f ? v : expm1f(v)) : v;
    }

    if (!FINAL) {
        __half2 hv[NH2];
#pragma unroll
        for (int k = 0; k < NH2; k++)
            hv[k] = __floats2half2_rn(vals[k*2+0], vals[k*2+1]);
        __half* op = (__half*)outp + (size_t)d * DT + colbase + lane * V;
        *(uint2*)op = *(uint2*)hv;
    } else {
        // DT=128, WPN=1, V=4: head-mean via xor-reduce over head lanes
#pragma unroll
        for (int off = 4; off <= 16; off <<= 1) {
#pragma unroll
            for (int k = 0; k < V; k++)
                vals[k] += __shfl_xor_sync(0xffffffffu, vals[k], off);
        }
        if (lane < 4) {
            float4 o = make_float4(vals[0] * 0.125f, vals[1] * 0.125f,
                                   vals[2] * 0.125f, vals[3] * 0.125f);
            ((float4*)((float*)outp + (size_t)d * OUTD))[lane] = o;
        }
    }
}

// ---------------- launch ----------------------------------------------------
extern "C" void kernel_launch(void* const* d_in, const int* in_sizes, int n_in,
                              void* d_out, int out_size)
{
    const float* x   = (const float*)d_in[0];
    const float* W1  = (const float*)d_in[1];
    const float* al1 = (const float*)d_in[2];
    const float* ar1 = (const float*)d_in[3];
    const float* b1  = (const float*)d_in[4];
    const float* W2  = (const float*)d_in[5];
    const float* al2 = (const float*)d_in[6];
    const float* ar2 = (const float*)d_in[7];
    const float* b2  = (const float*)d_in[8];
    const int*   src = (const int*)d_in[9];
    const int*   dst = (const int*)d_in[10];
    float* out = (float*)d_out;

    __half *x16, *W1h, *W2h, *feat1, *agg1, *feat2;
    float *el, *er;
    cudaGetSymbolAddress((void**)&x16,   g_x16);
    cudaGetSymbolAddress((void**)&W1h,   g_W1_16);
    cudaGetSymbolAddress((void**)&W2h,   g_W2_16);
    cudaGetSymbolAddress((void**)&feat1, g_feat1);
    cudaGetSymbolAddress((void**)&agg1,  g_agg1);
    cudaGetSymbolAddress((void**)&feat2, g_feat2);
    cudaGetSymbolAddress((void**)&el,    g_el);
    cudaGetSymbolAddress((void**)&er,    g_er);

    static bool attrDone = false;
    if (!attrDone) {
        cudaFuncSetAttribute((const void*)gemm_att_wmma<INF_, C1, HIDD>,
                             cudaFuncAttributeMaxDynamicSharedMemorySize, 64 * C1 * 4);
        cudaFuncSetAttribute((const void*)gemm_att_wmma<C1, C2, OUTD>,
                             cudaFuncAttributeMaxDynamicSharedMemorySize, 64 * C2 * 4);
        attrDone = true;
    }

    const int eBlocks    = (EE + 255) / 256;
    const int gemmBlocks = NNP / 64;
    const int agg1Blocks = (NN * 2 + 7) / 8;   // 2 warps/node
    const int agg2Blocks = (NN + 7) / 8;

    // CSR build (shared by both layers)
    k_zero_cnt<<<(NN + 255)/256, 256>>>();
    k_hist<<<eBlocks, 256>>>(dst);
    k_scan<<<1, 1024>>>();
    k_scatter<<<eBlocks, 256>>>(src, dst);

    // fp16 conversions
    k_convert<<<(NN*INF_ + 255)/256, 256>>>(x, W1, W2);

    // layer 1
    gemm_att_wmma<INF_, C1, HIDD><<<gemmBlocks, 256, 64*C1*4>>>(x16, W1h, al1, ar1,
                                                                feat1, el, er, NN);
    node_aggregate<C1, 2, true, false><<<agg1Blocks, 256>>>(feat1, el, er, b1, agg1);

    // layer 2 (head-mean fused)
    gemm_att_wmma<C1, C2, OUTD><<<gemmBlocks, 256, 64*C2*4>>>(agg1, W2h, al2, ar2,
                                                              feat2, el, er, NN);
    node_aggregate<C2, 1, false, true><<<agg2Blocks, 256>>>(feat2, el, er, b2, out);
}